// round 13
// baseline (speedup 1.0000x reference)
#include <cuda_runtime.h>
#include <cuda_bf16.h>
#include <math.h>

// Shapes (fixed)
#define BATCH 8
#define CH    512
#define NTOK  1024
#define LKV   2048
#define HEADS 8
#define HD    64
#define SCALE 0.125f
#define LOG2E 1.44269504089f

// Scratch (static device allocations; no cudaMalloc allowed)
__device__ __nv_bfloat16 g_Q[BATCH * CH * NTOK];   // bf16, pre-scaled by 0.125*log2e
__device__ __nv_bfloat16 g_K[BATCH * CH * LKV];
__device__ __nv_bfloat16 g_V[BATCH * CH * LKV];
__device__ __nv_bfloat16 g_Abf[BATCH * CH * NTOK]; // attn out bf16
__device__ float g_Z[BATCH * CH * NTOK];
// bf16 copies of inputs
__device__ __nv_bfloat16 g_fc[BATCH * CH * NTOK];
__device__ __nv_bfloat16 g_fp[BATCH * CH * NTOK];
__device__ __nv_bfloat16 g_fn[BATCH * CH * NTOK];
__device__ __nv_bfloat16 g_wq[CH * CH];
__device__ __nv_bfloat16 g_wk[CH * CH];
__device__ __nv_bfloat16 g_wv[CH * CH];
__device__ __nv_bfloat16 g_wo[CH * CH];

// ---------------------------------------------------------------------------
// helpers
// ---------------------------------------------------------------------------
__device__ __forceinline__ unsigned pk(float lo, float hi) {
    __nv_bfloat162 t = __floats2bfloat162_rn(lo, hi);
    return *reinterpret_cast<unsigned*>(&t);
}
__device__ __forceinline__ unsigned s2u(const void* p) {
    return (unsigned)__cvta_generic_to_shared(p);
}
__device__ __forceinline__ float ex2(float x) {
    float y;
    asm("ex2.approx.f32 %0, %1;" : "=f"(y) : "f"(x));
    return y;
}
__device__ __forceinline__ void mma16(float* c,
                                      unsigned a0, unsigned a1, unsigned a2, unsigned a3,
                                      unsigned b0, unsigned b1) {
    asm volatile(
        "mma.sync.aligned.m16n8k16.row.col.f32.bf16.bf16.f32 "
        "{%0,%1,%2,%3}, {%4,%5,%6,%7}, {%8,%9}, {%0,%1,%2,%3};"
        : "+f"(c[0]), "+f"(c[1]), "+f"(c[2]), "+f"(c[3])
        : "r"(a0), "r"(a1), "r"(a2), "r"(a3), "r"(b0), "r"(b1));
}
__device__ __forceinline__ void ldsm4t(unsigned& r0, unsigned& r1,
                                       unsigned& r2, unsigned& r3, unsigned addr) {
    asm volatile("ldmatrix.sync.aligned.m8n8.x4.trans.shared.b16 {%0,%1,%2,%3}, [%4];"
                 : "=r"(r0), "=r"(r1), "=r"(r2), "=r"(r3) : "r"(addr));
}
__device__ __forceinline__ void ldsm4(unsigned& r0, unsigned& r1,
                                      unsigned& r2, unsigned& r3, unsigned addr) {
    asm volatile("ldmatrix.sync.aligned.m8n8.x4.shared.b16 {%0,%1,%2,%3}, [%4];"
                 : "=r"(r0), "=r"(r1), "=r"(r2), "=r"(r3) : "r"(addr));
}
__device__ __forceinline__ void cpa16(unsigned dst, const void* src) {
    asm volatile("cp.async.cg.shared.global [%0], [%1], 16;" :: "r"(dst), "l"(src));
}

// ---------------------------------------------------------------------------
// One-time fp32 -> bf16 conversions (features + weights, one launch)
// ---------------------------------------------------------------------------
__global__ void __launch_bounds__(256) cvt_all(
    const float* __restrict__ fc, const float* __restrict__ fp,
    const float* __restrict__ fn, const float* __restrict__ Wq,
    const float* __restrict__ Wk, const float* __restrict__ Wv,
    const float* __restrict__ Wo)
{
    const float* src; __nv_bfloat16* dst; long nElem;
    switch (blockIdx.y) {
        case 0: src = fc; dst = g_fc; nElem = (long)BATCH * CH * NTOK; break;
        case 1: src = fp; dst = g_fp; nElem = (long)BATCH * CH * NTOK; break;
        case 2: src = fn; dst = g_fn; nElem = (long)BATCH * CH * NTOK; break;
        case 3: src = Wq; dst = g_wq; nElem = CH * CH; break;
        case 4: src = Wk; dst = g_wk; nElem = CH * CH; break;
        case 5: src = Wv; dst = g_wv; nElem = CH * CH; break;
        default:src = Wo; dst = g_wo; nElem = CH * CH; break;
    }
    long i = ((long)blockIdx.x * 256 + threadIdx.x) * 8;
    if (i >= nElem) return;
    float4 a = *(const float4*)&src[i];
    float4 b = *(const float4*)&src[i + 4];
    uint4 u = make_uint4(pk(a.x, a.y), pk(a.z, a.w), pk(b.x, b.y), pk(b.z, b.w));
    *(uint4*)&dst[i] = u;
}

// ---------------------------------------------------------------------------
// GEMM core: 128x128 tile, k-step 32, 3-stage cp.async, ldmatrix frags.
// ---------------------------------------------------------------------------
#define AST 40
#define BST 136
#define GA_ELTS (128 * AST)
#define GB_ELTS (32 * BST)
#define GST_ELTS (GA_ELTS + GB_ELTS)
#define GEMM_SMEM (3 * GST_ELTS * 2)      // 56832 B

__device__ __forceinline__ void gemm_issue(
    __nv_bfloat16* sA, __nv_bfloat16* sB,
    const __nv_bfloat16* __restrict__ W, const __nv_bfloat16* __restrict__ Xb,
    int ldx, int m0, int n0, int k0, int tid)
{
#pragma unroll
    for (int i = 0; i < 2; i++) {
        int c = i * 256 + tid;
        int r = c >> 2, kc = (c & 3) * 8;
        cpa16(s2u(&sA[r * AST + kc]), W + (long)(m0 + r) * 512 + k0 + kc);
    }
#pragma unroll
    for (int i = 0; i < 2; i++) {
        int c = i * 256 + tid;
        int r = c >> 4, nc = (c & 15) * 8;
        cpa16(s2u(&sB[r * BST + nc]), Xb + (long)(k0 + r) * ldx + n0 + nc);
    }
    asm volatile("cp.async.commit_group;");
}

template <bool OBF>
__device__ __forceinline__ void gemm_core(
    const __nv_bfloat16* __restrict__ W, const __nv_bfloat16* __restrict__ Xb,
    void* __restrict__ Obv, const float* __restrict__ Rb,
    int ldx, int ldc, int m0, int n0, float oscale)
{
    extern __shared__ __nv_bfloat16 gsm[];
    const int tid  = threadIdx.x;
    const int lane = tid & 31, warp = tid >> 5;
    const int wm = warp >> 2, wn = warp & 3;
    const int lq = lane >> 2, lk = lane & 3;
    const int t = lane >> 3, rr = lane & 7;

    __nv_bfloat16* sA[3]; __nv_bfloat16* sB[3];
#pragma unroll
    for (int s = 0; s < 3; s++) {
        sA[s] = gsm + s * GST_ELTS;
        sB[s] = sA[s] + GA_ELTS;
    }

    float acc[4][4][4];
#pragma unroll
    for (int mi = 0; mi < 4; mi++)
#pragma unroll
        for (int ni = 0; ni < 4; ni++)
#pragma unroll
            for (int r = 0; r < 4; r++) acc[mi][ni][r] = 0.f;

    // Per-thread ldmatrix base offsets (bytes)
    const unsigned ath = (unsigned)(((wm * 64 + rr + (t & 1) * 8) * AST + (t >> 1) * 8) * 2);
    const unsigned bth = (unsigned)(((rr + (t & 1) * 8) * BST + wn * 32 + (t >> 1) * 8) * 2);
    unsigned uA[3], uB[3];
#pragma unroll
    for (int s = 0; s < 3; s++) {
        uA[s] = s2u(sA[s]) + ath;
        uB[s] = s2u(sB[s]) + bth;
    }

    gemm_issue(sA[0], sB[0], W, Xb, ldx, m0, n0, 0, tid);
    gemm_issue(sA[1], sB[1], W, Xb, ldx, m0, n0, 32, tid);

    int stg = 0;
    for (int it = 0; it < 16; it++) {
        // No-redundant-issue scheme: at it=15 only stage-15's group can be in
        // flight, so a full drain is required (wait_group 1 would skip it).
        if (it == 15) asm volatile("cp.async.wait_group 0;");
        else          asm volatile("cp.async.wait_group 1;");
        __syncthreads();

#pragma unroll
        for (int ss = 0; ss < 2; ss++) {
            const int kb = ss * 16;
            unsigned af[4][4];
#pragma unroll
            for (int mi = 0; mi < 4; mi++)
                ldsm4(af[mi][0], af[mi][1], af[mi][2], af[mi][3],
                      uA[stg] + (mi * 16 * AST + kb) * 2);
            unsigned bfv[4][2];
#pragma unroll
            for (int p = 0; p < 2; p++)
                ldsm4t(bfv[2 * p][0], bfv[2 * p][1], bfv[2 * p + 1][0], bfv[2 * p + 1][1],
                       uB[stg] + (kb * BST + p * 16) * 2);
#pragma unroll
            for (int mi = 0; mi < 4; mi++)
#pragma unroll
                for (int ni = 0; ni < 4; ni++)
                    mma16(acc[mi][ni], af[mi][0], af[mi][1], af[mi][2], af[mi][3],
                          bfv[ni][0], bfv[ni][1]);
        }

        // Issue stage it+2 (target stage was consumed at it-1; all threads
        // passed sync(it) which follows their compute(it-1))
        if (it + 2 < 16) {
            const int ws = (stg + 2 >= 3) ? stg - 1 : stg + 2;
            gemm_issue(sA[ws], sB[ws], W, Xb, ldx, m0, n0, (it + 2) * 32, tid);
        }
        stg = (stg == 2) ? 0 : stg + 1;
    }

#pragma unroll
    for (int mi = 0; mi < 4; mi++) {
#pragma unroll
        for (int ni = 0; ni < 4; ni++) {
            const int row = m0 + wm * 64 + mi * 16 + lq;
            const int col = n0 + wn * 32 + ni * 8 + 2 * lk;
            const long o0 = (long)row * ldc + col;
            const long o1 = (long)(row + 8) * ldc + col;
            if (OBF) {
                __nv_bfloat16* Ob = (__nv_bfloat16*)Obv;
                *(unsigned*)&Ob[o0] = pk(acc[mi][ni][0] * oscale, acc[mi][ni][1] * oscale);
                *(unsigned*)&Ob[o1] = pk(acc[mi][ni][2] * oscale, acc[mi][ni][3] * oscale);
            } else {
                float* Ob = (float*)Obv;
                float2 v0 = make_float2(acc[mi][ni][0], acc[mi][ni][1]);
                float2 v1 = make_float2(acc[mi][ni][2], acc[mi][ni][3]);
                float2 r0 = *(const float2*)&Rb[o0];
                float2 r1 = *(const float2*)&Rb[o1];
                v0.x += r0.x; v0.y += r0.y;
                v1.x += r1.x; v1.y += r1.y;
                *(float2*)&Ob[o0] = v0;
                *(float2*)&Ob[o1] = v1;
            }
        }
    }
}

// All 5 projections in ONE launch; Q pre-scaled by 0.125*log2e
__global__ void __launch_bounds__(256, 2) proj5()
{
    const int z = blockIdx.z;
    const int b = z & 7, job = z >> 3;
    const long sN = (long)CH * NTOK, sL = (long)CH * LKV;
    const __nv_bfloat16* W; const __nv_bfloat16* X; __nv_bfloat16* O;
    int ldc; float osc = 1.f;
    switch (job) {
        case 0: W = g_wq; X = g_fc + b * sN; O = g_Q + b * sN;        ldc = NTOK; osc = SCALE * LOG2E; break;
        case 1: W = g_wk; X = g_fp + b * sN; O = g_K + b * sL;        ldc = LKV;  break;
        case 2: W = g_wk; X = g_fn + b * sN; O = g_K + b * sL + NTOK; ldc = LKV;  break;
        case 3: W = g_wv; X = g_fp + b * sN; O = g_V + b * sL;        ldc = LKV;  break;
        default:W = g_wv; X = g_fn + b * sN; O = g_V + b * sL + NTOK; ldc = LKV;  break;
    }
    gemm_core<true>(W, X, O, nullptr, NTOK, ldc, blockIdx.y * 128, blockIdx.x * 128, osc);
}

// Output projection + residual
__global__ void __launch_bounds__(256, 2) gemm_wo(const float* __restrict__ R)
{
    const long sN = (long)CH * NTOK;
    gemm_core<false>(g_wo, g_Abf + blockIdx.z * sN, g_Z + blockIdx.z * sN,
                     R + blockIdx.z * sN, NTOK, NTOK,
                     blockIdx.y * 128, blockIdx.x * 128, 1.f);
}

// ---------------------------------------------------------------------------
// Flash attention: 3-stage KV pipeline, ldmatrix for K AND V, P in registers,
// exp2-domain softmax without online max.
// ---------------------------------------------------------------------------
#define QSTR 136
#define KSTR 72
#define VSTR 72
#define ESTR 72
#define Q_ELTS (64 * QSTR)
#define K_ELTS (64 * KSTR)
#define V_ELTS (64 * VSTR)
#define KV_BYTES ((K_ELTS + V_ELTS) * 2)                    // 18432 per stage
#define FLASH_SMEM (Q_ELTS * 2 + 3 * KV_BYTES)              // 72704 B

__global__ void __launch_bounds__(256, 2) flash_bf16(
    const __nv_bfloat16* __restrict__ Q, const __nv_bfloat16* __restrict__ K,
    const __nv_bfloat16* __restrict__ V, __nv_bfloat16* __restrict__ A)
{
    extern __shared__ char smraw[];
    __nv_bfloat16* Qs = (__nv_bfloat16*)smraw;
    __nv_bfloat16* KV0 = Qs + Q_ELTS;   // stage s: K at KV0 + s*(K+V), V after K

    const int tid  = threadIdx.x;
    const int lane = tid & 31;
    const int warp = tid >> 5;
    const int qw = warp * 16;
    const int lq = lane >> 2, lk = lane & 3;
    const int t = lane >> 3, rr = lane & 7;
    const int nq0 = blockIdx.x * 128;
    const int h = blockIdx.y, b = blockIdx.z;

    const __nv_bfloat16* Qb = Q + ((long)b * CH + h * HD) * NTOK + nq0;
    const __nv_bfloat16* Kb = K + ((long)b * CH + h * HD) * LKV;
    const __nv_bfloat16* Vb = V + ((long)b * CH + h * HD) * LKV;

    // Issue KV tile at m0k into stage s
    auto kv_issue = [&](int s, int m0k) {
        __nv_bfloat16* Ks = KV0 + s * (K_ELTS + V_ELTS);
        __nv_bfloat16* Vs = Ks + K_ELTS;
#pragma unroll
        for (int i = 0; i < 2; i++) {
            int c = i * 256 + tid;
            int d = c >> 3, e = (c & 7) * 8;
            cpa16(s2u(&Ks[d * KSTR + e]), Kb + (long)d * LKV + m0k + e);
            cpa16(s2u(&Vs[d * VSTR + e]), Vb + (long)d * LKV + m0k + e);
        }
        asm volatile("cp.async.commit_group;");
    };

    // Prologue: Q group, then KV stages 0,1
#pragma unroll
    for (int r = 0; r < 4; r++) {
        int f = r * 256 + tid;
        int d = f >> 4, e = (f & 15) * 8;
        cpa16(s2u(&Qs[d * QSTR + e]), Qb + (long)d * NTOK + e);
    }
    asm volatile("cp.async.commit_group;");
    kv_issue(0, 0);
    kv_issue(1, 64);

    // Wait Q, hoist Q fragments (loop-invariant)
    asm volatile("cp.async.wait_group 2;");
    __syncthreads();
    unsigned qa[4][4];
    {
        const unsigned qbase = s2u(Qs) +
            ((rr + (t >> 1) * 8) * QSTR + qw + (t & 1) * 8) * 2;
#pragma unroll
        for (int k8 = 0; k8 < 4; k8++)
            ldsm4t(qa[k8][0], qa[k8][1], qa[k8][2], qa[k8][3],
                   qbase + k8 * 16 * QSTR * 2);
    }

    // Per-thread ldmatrix bases (bytes, relative to stage-0 K/V)
    const unsigned kth = ((rr + (t & 1) * 8) * KSTR + (t >> 1) * 8) * 2;   // trans
    const unsigned vth = ((rr + (t >> 1) * 8) * VSTR + (t & 1) * 8) * 2;   // non-trans
    const unsigned uKb = s2u(KV0) + kth;
    const unsigned uVb = s2u(KV0 + K_ELTS) + vth;

    float o[8][4];
#pragma unroll
    for (int ni = 0; ni < 8; ni++)
#pragma unroll
        for (int r = 0; r < 4; r++) o[ni][r] = 0.f;
    float rs0 = 0.f, rs1 = 0.f;

    int stg = 0;
    for (int mt = 0; mt < 32; mt++) {
        if (mt == 31) asm volatile("cp.async.wait_group 0;");
        else          asm volatile("cp.async.wait_group 1;");
        __syncthreads();

        const unsigned uK = uKb + stg * KV_BYTES;
        const unsigned uV = uVb + stg * KV_BYTES;

        // S = Q^T K : q16 x kv64 (log2 units)
        float s[8][4];
#pragma unroll
        for (int ni = 0; ni < 8; ni++)
#pragma unroll
            for (int r = 0; r < 4; r++) s[ni][r] = 0.f;
#pragma unroll
        for (int k8 = 0; k8 < 4; k8++) {
#pragma unroll
            for (int p = 0; p < 4; p++) {
                unsigned b00, b01, b10, b11;
                ldsm4t(b00, b01, b10, b11, uK + (k8 * 16 * KSTR + p * 16) * 2);
                mma16(s[2 * p],     qa[k8][0], qa[k8][1], qa[k8][2], qa[k8][3], b00, b01);
                mma16(s[2 * p + 1], qa[k8][0], qa[k8][1], qa[k8][2], qa[k8][3], b10, b11);
            }
        }

        // P = 2^s, local denominator (no max, no per-iter shuffles)
#pragma unroll
        for (int ni = 0; ni < 8; ni++) {
            s[ni][0] = ex2(s[ni][0]);
            s[ni][1] = ex2(s[ni][1]);
            s[ni][2] = ex2(s[ni][2]);
            s[ni][3] = ex2(s[ni][3]);
            rs0 += s[ni][0] + s[ni][1];
            rs1 += s[ni][2] + s[ni][3];
        }

        // O += P V : A-frag = S C-frag; V B-frags via non-trans ldmatrix
#pragma unroll
        for (int k8 = 0; k8 < 4; k8++) {
            unsigned a0 = pk(s[2 * k8][0],     s[2 * k8][1]);
            unsigned a1 = pk(s[2 * k8][2],     s[2 * k8][3]);
            unsigned a2 = pk(s[2 * k8 + 1][0], s[2 * k8 + 1][1]);
            unsigned a3 = pk(s[2 * k8 + 1][2], s[2 * k8 + 1][3]);
#pragma unroll
            for (int p = 0; p < 4; p++) {
                unsigned b0, b1, b2, b3;
                ldsm4(b0, b1, b2, b3, uV + (p * 16 * VSTR + k8 * 16) * 2);
                mma16(o[2 * p],     a0, a1, a2, a3, b0, b1);
                mma16(o[2 * p + 1], a0, a1, a2, a3, b2, b3);
            }
        }

        // Issue KV(mt+2) into the stage consumed at mt-1 (safe past sync(mt))
        if (mt <= 29) {
            const int ws = (stg + 2 >= 3) ? stg - 1 : stg + 2;
            kv_issue(ws, (mt + 2) * 64);
        }
        stg = (stg == 2) ? 0 : stg + 1;
    }

    // Denominator reduction over the 4 lanes sharing lq
    rs0 += __shfl_xor_sync(0xffffffffu, rs0, 1);
    rs0 += __shfl_xor_sync(0xffffffffu, rs0, 2);
    rs1 += __shfl_xor_sync(0xffffffffu, rs1, 1);
    rs1 += __shfl_xor_sync(0xffffffffu, rs1, 2);
    const float inv0 = 1.f / rs0, inv1 = 1.f / rs1;

    // Epilogue: all cp.async drained (wait 0 at mt=31). Reuse smem front.
    __syncthreads();
    __nv_bfloat16* Es = (__nv_bfloat16*)smraw;   // [128][ESTR]
#pragma unroll
    for (int ni = 0; ni < 8; ni++) {
        const int col = ni * 8 + 2 * lk;
        *(unsigned*)&Es[(qw + lq) * ESTR + col]     = pk(o[ni][0] * inv0, o[ni][1] * inv0);
        *(unsigned*)&Es[(qw + 8 + lq) * ESTR + col] = pk(o[ni][2] * inv1, o[ni][3] * inv1);
    }
    __syncthreads();
    __nv_bfloat16* Ab = A + ((long)b * CH + h * HD) * NTOK + nq0;
#pragma unroll
    for (int r = 0; r < 4; r++) {
        int f = r * 256 + tid;
        int d = f >> 4, qc = (f & 15) * 8;
        unsigned short tmp[8];
#pragma unroll
        for (int j = 0; j < 8; j++)
            tmp[j] = *(const unsigned short*)&Es[(qc + j) * ESTR + d];
        *(uint4*)&Ab[(long)d * NTOK + qc] = *(uint4*)tmp;
    }
}

// ---------------------------------------------------------------------------
// LayerNorm: single gmem read, smem-cached.
// ---------------------------------------------------------------------------
#define LN_SMEM (512 * 36 * 4)
__global__ void __launch_bounds__(256, 2) ln512(
    const float* __restrict__ Z, const float* __restrict__ gamma,
    const float* __restrict__ beta, float* __restrict__ O)
{
    extern __shared__ float sc[];   // [512][36]
    __shared__ float ss[8][33], sq2[8][33];
    __shared__ float mu[32], rsd[32];
    const int tid = threadIdx.x;
    const int w = tid >> 5, l = tid & 31;
    const int n0 = blockIdx.x * 32;
    const int b = blockIdx.y;
    const float* Zb = Z + (long)b * CH * NTOK + n0;

#pragma unroll
    for (int k = 0; k < 16; k++) {
        int idx = k * 256 + tid;
        int c = idx >> 3, col = (idx & 7) * 4;
        float4 v = *(const float4*)&Zb[(long)c * NTOK + col];
        *(float4*)&sc[c * 36 + col] = v;
    }
    __syncthreads();

    float s = 0.f, q = 0.f;
#pragma unroll 8
    for (int c = w; c < CH; c += 8) {
        float v = sc[c * 36 + l];
        s += v; q += v * v;
    }
    ss[w][l] = s; sq2[w][l] = q;
    __syncthreads();
    if (w == 0) {
        float S = 0.f, Qq = 0.f;
#pragma unroll
        for (int i = 0; i < 8; i++) { S += ss[i][l]; Qq += sq2[i][l]; }
        float m = S * (1.f / CH);
        float var = Qq * (1.f / CH) - m * m;
        mu[l] = m;
        rsd[l] = rsqrtf(var + 1e-5f);
    }
    __syncthreads();

    float* Ob = O + (long)b * CH * NTOK + n0;
    const float M = mu[l], RS = rsd[l];
#pragma unroll 8
    for (int c = w; c < CH; c += 8) {
        float v = sc[c * 36 + l];
        Ob[(long)c * NTOK + l] = (v - M) * RS * gamma[c] + beta[c];
    }
}

// ---------------------------------------------------------------------------
extern "C" void kernel_launch(void* const* d_in, const int* in_sizes, int n_in,
                              void* d_out, int out_size)
{
    const float* f_curr = (const float*)d_in[0];
    const float* f_prev = (const float*)d_in[1];
    const float* f_next = (const float*)d_in[2];
    const float* Wq = (const float*)d_in[3];
    const float* Wk = (const float*)d_in[4];
    const float* Wv = (const float*)d_in[5];
    const float* Wo = (const float*)d_in[6];
    const float* gamma = (const float*)d_in[7];
    const float* beta = (const float*)d_in[8];
    float* out = (float*)d_out;

    __nv_bfloat16 *Qp, *Kp, *Vp, *Ap;
    float *Zp;
    cudaGetSymbolAddress((void**)&Qp, g_Q);
    cudaGetSymbolAddress((void**)&Kp, g_K);
    cudaGetSymbolAddress((void**)&Vp, g_V);
    cudaGetSymbolAddress((void**)&Ap, g_Abf);
    cudaGetSymbolAddress((void**)&Zp, g_Z);

    cudaFuncSetAttribute(proj5, cudaFuncAttributeMaxDynamicSharedMemorySize, GEMM_SMEM);
    cudaFuncSetAttribute(gemm_wo, cudaFuncAttributeMaxDynamicSharedMemorySize, GEMM_SMEM);
    cudaFuncSetAttribute(flash_bf16, cudaFuncAttributeMaxDynamicSharedMemorySize, FLASH_SMEM);
    cudaFuncSetAttribute(ln512, cudaFuncAttributeMaxDynamicSharedMemorySize, LN_SMEM);

    // One-time input conversion to bf16
    cvt_all<<<dim3(2048, 7), 256>>>(f_curr, f_prev, f_next, Wq, Wk, Wv, Wo);

    // All 5 projections in one launch
    proj5<<<dim3(8, 4, 40), 256, GEMM_SMEM>>>();

    // Attention
    flash_bf16<<<dim3(8, HEADS, BATCH), 256, FLASH_SMEM>>>(Qp, Kp, Vp, Ap);

    // Output projection + residual
    gemm_wo<<<dim3(8, 4, 8), 256, GEMM_SMEM>>>(f_curr);

    // LayerNorm
    ln512<<<dim3(32, BATCH), 256, LN_SMEM>>>(Zp, gamma, beta, out);
}

// round 14
// speedup vs baseline: 1.3579x; 1.3579x over previous
#include <cuda_runtime.h>
#include <cuda_bf16.h>
#include <math.h>

// Shapes (fixed)
#define BATCH 8
#define CH    512
#define NTOK  1024
#define LKV   2048
#define HEADS 8
#define HD    64
#define SCALE 0.125f
#define LOG2E 1.44269504089f

// Scratch (static device allocations; no cudaMalloc allowed)
__device__ __nv_bfloat16 g_Q[BATCH * CH * NTOK];   // bf16, pre-scaled by 0.125*log2e
__device__ __nv_bfloat16 g_K[BATCH * CH * LKV];
__device__ __nv_bfloat16 g_V[BATCH * CH * LKV];
__device__ __nv_bfloat16 g_Abf[BATCH * CH * NTOK]; // attn out bf16
__device__ float g_Z[BATCH * CH * NTOK];
// bf16 copies of inputs
__device__ __nv_bfloat16 g_fc[BATCH * CH * NTOK];
__device__ __nv_bfloat16 g_fp[BATCH * CH * NTOK];
__device__ __nv_bfloat16 g_fn[BATCH * CH * NTOK];
__device__ __nv_bfloat16 g_wq[CH * CH];
__device__ __nv_bfloat16 g_wk[CH * CH];
__device__ __nv_bfloat16 g_wv[CH * CH];
__device__ __nv_bfloat16 g_wo[CH * CH];

// ---------------------------------------------------------------------------
// helpers
// ---------------------------------------------------------------------------
__device__ __forceinline__ unsigned pk(float lo, float hi) {
    __nv_bfloat162 t = __floats2bfloat162_rn(lo, hi);
    return *reinterpret_cast<unsigned*>(&t);
}
__device__ __forceinline__ unsigned s2u(const void* p) {
    return (unsigned)__cvta_generic_to_shared(p);
}
__device__ __forceinline__ float ex2(float x) {
    float y;
    asm("ex2.approx.f32 %0, %1;" : "=f"(y) : "f"(x));
    return y;
}
__device__ __forceinline__ void mma16(float* c,
                                      unsigned a0, unsigned a1, unsigned a2, unsigned a3,
                                      unsigned b0, unsigned b1) {
    asm volatile(
        "mma.sync.aligned.m16n8k16.row.col.f32.bf16.bf16.f32 "
        "{%0,%1,%2,%3}, {%4,%5,%6,%7}, {%8,%9}, {%0,%1,%2,%3};"
        : "+f"(c[0]), "+f"(c[1]), "+f"(c[2]), "+f"(c[3])
        : "r"(a0), "r"(a1), "r"(a2), "r"(a3), "r"(b0), "r"(b1));
}
__device__ __forceinline__ void ldsm4t(unsigned& r0, unsigned& r1,
                                       unsigned& r2, unsigned& r3, unsigned addr) {
    asm volatile("ldmatrix.sync.aligned.m8n8.x4.trans.shared.b16 {%0,%1,%2,%3}, [%4];"
                 : "=r"(r0), "=r"(r1), "=r"(r2), "=r"(r3) : "r"(addr));
}
__device__ __forceinline__ void ldsm4(unsigned& r0, unsigned& r1,
                                      unsigned& r2, unsigned& r3, unsigned addr) {
    asm volatile("ldmatrix.sync.aligned.m8n8.x4.shared.b16 {%0,%1,%2,%3}, [%4];"
                 : "=r"(r0), "=r"(r1), "=r"(r2), "=r"(r3) : "r"(addr));
}
__device__ __forceinline__ void cpa16(unsigned dst, const void* src) {
    asm volatile("cp.async.cg.shared.global [%0], [%1], 16;" :: "r"(dst), "l"(src));
}

// ---------------------------------------------------------------------------
// One-time fp32 -> bf16 conversions (features + weights, one launch)
// ---------------------------------------------------------------------------
__global__ void __launch_bounds__(256) cvt_all(
    const float* __restrict__ fc, const float* __restrict__ fp,
    const float* __restrict__ fn, const float* __restrict__ Wq,
    const float* __restrict__ Wk, const float* __restrict__ Wv,
    const float* __restrict__ Wo)
{
    const float* src; __nv_bfloat16* dst; long nElem;
    switch (blockIdx.y) {
        case 0: src = fc; dst = g_fc; nElem = (long)BATCH * CH * NTOK; break;
        case 1: src = fp; dst = g_fp; nElem = (long)BATCH * CH * NTOK; break;
        case 2: src = fn; dst = g_fn; nElem = (long)BATCH * CH * NTOK; break;
        case 3: src = Wq; dst = g_wq; nElem = CH * CH; break;
        case 4: src = Wk; dst = g_wk; nElem = CH * CH; break;
        case 5: src = Wv; dst = g_wv; nElem = CH * CH; break;
        default:src = Wo; dst = g_wo; nElem = CH * CH; break;
    }
    long i = ((long)blockIdx.x * 256 + threadIdx.x) * 8;
    if (i >= nElem) return;
    float4 a = *(const float4*)&src[i];
    float4 b = *(const float4*)&src[i + 4];
    uint4 u = make_uint4(pk(a.x, a.y), pk(a.z, a.w), pk(b.x, b.y), pk(b.z, b.w));
    *(uint4*)&dst[i] = u;
}

// ---------------------------------------------------------------------------
// GEMM core (R11 2-stage structure + ldmatrix A-feed):
// Out[m][n] = sum_k W[m][k] * X[k][n]. Block tile 128x128, k-step 32.
// ---------------------------------------------------------------------------
#define AST 40
#define BST 136

struct SmemGemm {
    __nv_bfloat16 A[2][128][AST];
    __nv_bfloat16 B[2][32][BST];
};

__device__ __forceinline__ void gemm_issue(
    __nv_bfloat16 (*sA)[AST], __nv_bfloat16 (*sB)[BST],
    const __nv_bfloat16* __restrict__ W, const __nv_bfloat16* __restrict__ Xb,
    int ldx, int m0, int n0, int k0, int tid)
{
#pragma unroll
    for (int i = 0; i < 2; i++) {
        int c = i * 256 + tid;
        int r = c >> 2, kc = (c & 3) * 8;
        cpa16(s2u(&sA[r][kc]), W + (long)(m0 + r) * 512 + k0 + kc);
    }
#pragma unroll
    for (int i = 0; i < 2; i++) {
        int c = i * 256 + tid;
        int r = c >> 4, nc = (c & 15) * 8;
        cpa16(s2u(&sB[r][nc]), Xb + (long)(k0 + r) * ldx + n0 + nc);
    }
    asm volatile("cp.async.commit_group;");
}

template <bool OBF>
__device__ __forceinline__ void gemm_core(
    const __nv_bfloat16* __restrict__ W, const __nv_bfloat16* __restrict__ Xb,
    void* __restrict__ Obv, const float* __restrict__ Rb,
    int ldx, int ldc, int m0, int n0, float oscale, SmemGemm* S)
{
    const int tid  = threadIdx.x;
    const int lane = tid & 31, warp = tid >> 5;
    const int wm = warp >> 2, wn = warp & 3;
    const int lq = lane >> 2, lk = lane & 3;
    const int t = lane >> 3, rr = lane & 7;

    float acc[4][4][4];
#pragma unroll
    for (int mi = 0; mi < 4; mi++)
#pragma unroll
        for (int ni = 0; ni < 4; ni++)
#pragma unroll
            for (int r = 0; r < 4; r++) acc[mi][ni][r] = 0.f;

    // Per-thread ldmatrix base addresses for both buffers (scalar, no arrays)
    const unsigned ath = (unsigned)(((wm * 64 + rr + (t & 1) * 8) * AST + (t >> 1) * 8) * 2);
    const unsigned bth = (unsigned)(((rr + (t & 1) * 8) * BST + wn * 32 + (t >> 1) * 8) * 2);
    const unsigned uA0 = s2u(&S->A[0][0][0]) + ath;
    const unsigned uA1 = s2u(&S->A[1][0][0]) + ath;
    const unsigned uB0 = s2u(&S->B[0][0][0]) + bth;
    const unsigned uB1 = s2u(&S->B[1][0][0]) + bth;

    gemm_issue(S->A[0], S->B[0], W, Xb, ldx, m0, n0, 0, tid);

    int buf = 0;
    for (int k0 = 0; k0 < 512; k0 += 32) {
        const bool has = (k0 + 32) < 512;
        if (has) gemm_issue(S->A[buf ^ 1], S->B[buf ^ 1], W, Xb, ldx, m0, n0, k0 + 32, tid);
        if (has) asm volatile("cp.async.wait_group 1;");
        else     asm volatile("cp.async.wait_group 0;");
        __syncthreads();

        const unsigned uA = buf ? uA1 : uA0;
        const unsigned uB = buf ? uB1 : uB0;
#pragma unroll
        for (int ss = 0; ss < 2; ss++) {
            const int kb = ss * 16;
            unsigned af[4][4];
#pragma unroll
            for (int mi = 0; mi < 4; mi++)
                ldsm4(af[mi][0], af[mi][1], af[mi][2], af[mi][3],
                      uA + (mi * 16 * AST + kb) * 2);
            unsigned bfv[4][2];
#pragma unroll
            for (int p = 0; p < 2; p++)
                ldsm4t(bfv[2 * p][0], bfv[2 * p][1], bfv[2 * p + 1][0], bfv[2 * p + 1][1],
                       uB + (kb * BST + p * 16) * 2);
#pragma unroll
            for (int mi = 0; mi < 4; mi++)
#pragma unroll
                for (int ni = 0; ni < 4; ni++)
                    mma16(acc[mi][ni], af[mi][0], af[mi][1], af[mi][2], af[mi][3],
                          bfv[ni][0], bfv[ni][1]);
        }
        __syncthreads();
        buf ^= 1;
    }

#pragma unroll
    for (int mi = 0; mi < 4; mi++) {
#pragma unroll
        for (int ni = 0; ni < 4; ni++) {
            const int row = m0 + wm * 64 + mi * 16 + lq;
            const int col = n0 + wn * 32 + ni * 8 + 2 * lk;
            const long o0 = (long)row * ldc + col;
            const long o1 = (long)(row + 8) * ldc + col;
            if (OBF) {
                __nv_bfloat16* Ob = (__nv_bfloat16*)Obv;
                *(unsigned*)&Ob[o0] = pk(acc[mi][ni][0] * oscale, acc[mi][ni][1] * oscale);
                *(unsigned*)&Ob[o1] = pk(acc[mi][ni][2] * oscale, acc[mi][ni][3] * oscale);
            } else {
                float* Ob = (float*)Obv;
                float2 v0 = make_float2(acc[mi][ni][0], acc[mi][ni][1]);
                float2 v1 = make_float2(acc[mi][ni][2], acc[mi][ni][3]);
                float2 r0 = *(const float2*)&Rb[o0];
                float2 r1 = *(const float2*)&Rb[o1];
                v0.x += r0.x; v0.y += r0.y;
                v1.x += r1.x; v1.y += r1.y;
                *(float2*)&Ob[o0] = v0;
                *(float2*)&Ob[o1] = v1;
            }
        }
    }
}

// All 5 projections in ONE launch; Q pre-scaled by 0.125*log2e
__global__ void __launch_bounds__(256, 2) proj5()
{
    __shared__ SmemGemm S;
    const int z = blockIdx.z;
    const int b = z & 7, job = z >> 3;
    const long sN = (long)CH * NTOK, sL = (long)CH * LKV;
    const __nv_bfloat16* W; const __nv_bfloat16* X; __nv_bfloat16* O;
    int ldc; float osc = 1.f;
    switch (job) {
        case 0: W = g_wq; X = g_fc + b * sN; O = g_Q + b * sN;        ldc = NTOK; osc = SCALE * LOG2E; break;
        case 1: W = g_wk; X = g_fp + b * sN; O = g_K + b * sL;        ldc = LKV;  break;
        case 2: W = g_wk; X = g_fn + b * sN; O = g_K + b * sL + NTOK; ldc = LKV;  break;
        case 3: W = g_wv; X = g_fp + b * sN; O = g_V + b * sL;        ldc = LKV;  break;
        default:W = g_wv; X = g_fn + b * sN; O = g_V + b * sL + NTOK; ldc = LKV;  break;
    }
    gemm_core<true>(W, X, O, nullptr, NTOK, ldc, blockIdx.y * 128, blockIdx.x * 128, osc, &S);
}

// Output projection + residual
__global__ void __launch_bounds__(256, 2) gemm_wo(const float* __restrict__ R)
{
    __shared__ SmemGemm S;
    const long sN = (long)CH * NTOK;
    gemm_core<false>(g_wo, g_Abf + blockIdx.z * sN, g_Z + blockIdx.z * sN,
                     R + blockIdx.z * sN, NTOK, NTOK,
                     blockIdx.y * 128, blockIdx.x * 128, 1.f, &S);
}

// ---------------------------------------------------------------------------
// Flash attention (R11 2-stage structure + ldmatrix V-feed):
// P in registers, exp2-domain softmax without online max.
// ---------------------------------------------------------------------------
#define QSTR 136
#define KSTR 72
#define VSTR 72
#define ESTR 72
#define Q_ELTS (64 * QSTR)
#define K_ELTS (64 * KSTR)
#define V_ELTS (64 * VSTR)
#define FLASH_SMEM ((Q_ELTS + 2 * K_ELTS + 2 * V_ELTS) * 2)   // 54272 B

__global__ void __launch_bounds__(256, 2) flash_bf16(
    const __nv_bfloat16* __restrict__ Q, const __nv_bfloat16* __restrict__ K,
    const __nv_bfloat16* __restrict__ V, __nv_bfloat16* __restrict__ A)
{
    extern __shared__ char smraw[];
    __nv_bfloat16* Qs = (__nv_bfloat16*)smraw;
    __nv_bfloat16* Ks = Qs + Q_ELTS;          // 2 buffers
    __nv_bfloat16* Vs = Ks + 2 * K_ELTS;      // 2 buffers

    const int tid  = threadIdx.x;
    const int lane = tid & 31;
    const int warp = tid >> 5;
    const int qw = warp * 16;
    const int lq = lane >> 2, lk = lane & 3;
    const int t = lane >> 3, rr = lane & 7;
    const int nq0 = blockIdx.x * 128;
    const int h = blockIdx.y, b = blockIdx.z;

    const __nv_bfloat16* Qb = Q + ((long)b * CH + h * HD) * NTOK + nq0;
    const __nv_bfloat16* Kb = K + ((long)b * CH + h * HD) * LKV;
    const __nv_bfloat16* Vb = V + ((long)b * CH + h * HD) * LKV;

    // Prologue: Q in its own group, then KV tile 0
#pragma unroll
    for (int r = 0; r < 4; r++) {
        int f = r * 256 + tid;
        int d = f >> 4, e = (f & 15) * 8;
        cpa16(s2u(&Qs[d * QSTR + e]), Qb + (long)d * NTOK + e);
    }
    asm volatile("cp.async.commit_group;");
#pragma unroll
    for (int i = 0; i < 2; i++) {
        int c = i * 256 + tid;
        int d = c >> 3, e = (c & 7) * 8;
        cpa16(s2u(&Ks[d * KSTR + e]), Kb + (long)d * LKV + e);
        cpa16(s2u(&Vs[d * VSTR + e]), Vb + (long)d * LKV + e);
    }
    asm volatile("cp.async.commit_group;");

    // Wait Q, hoist Q fragments (loop-invariant)
    asm volatile("cp.async.wait_group 1;");
    __syncthreads();
    unsigned qa[4][4];
    {
        const unsigned qbase = s2u(Qs) +
            ((rr + (t >> 1) * 8) * QSTR + qw + (t & 1) * 8) * 2;
#pragma unroll
        for (int k8 = 0; k8 < 4; k8++)
            ldsm4t(qa[k8][0], qa[k8][1], qa[k8][2], qa[k8][3],
                   qbase + k8 * 16 * QSTR * 2);
    }

    // Per-thread ldmatrix bases, both buffers (scalar, no arrays)
    const unsigned kth = ((rr + (t & 1) * 8) * KSTR + (t >> 1) * 8) * 2;   // trans
    const unsigned vth = ((rr + (t >> 1) * 8) * VSTR + (t & 1) * 8) * 2;   // non-trans
    const unsigned uK0 = s2u(Ks) + kth, uK1 = s2u(Ks + K_ELTS) + kth;
    const unsigned uV0 = s2u(Vs) + vth, uV1 = s2u(Vs + V_ELTS) + vth;

    float o[8][4];
#pragma unroll
    for (int ni = 0; ni < 8; ni++)
#pragma unroll
        for (int r = 0; r < 4; r++) o[ni][r] = 0.f;
    float rs0 = 0.f, rs1 = 0.f;

    int buf = 0;
    for (int mt = 0; mt < 32; mt++) {
        if (mt < 31) {
            const int m0n = (mt + 1) * 64;
            __nv_bfloat16* Kd = Ks + (buf ^ 1) * K_ELTS;
            __nv_bfloat16* Vd = Vs + (buf ^ 1) * V_ELTS;
#pragma unroll
            for (int i = 0; i < 2; i++) {
                int c = i * 256 + tid;
                int d = c >> 3, e = (c & 7) * 8;
                cpa16(s2u(&Kd[d * KSTR + e]), Kb + (long)d * LKV + m0n + e);
                cpa16(s2u(&Vd[d * VSTR + e]), Vb + (long)d * LKV + m0n + e);
            }
            asm volatile("cp.async.commit_group;");
            asm volatile("cp.async.wait_group 1;");
        } else {
            asm volatile("cp.async.wait_group 0;");
        }
        __syncthreads();

        const unsigned uK = buf ? uK1 : uK0;
        const unsigned uV = buf ? uV1 : uV0;

        // S = Q^T K : q16 x kv64 (log2 units)
        float s[8][4];
#pragma unroll
        for (int ni = 0; ni < 8; ni++)
#pragma unroll
            for (int r = 0; r < 4; r++) s[ni][r] = 0.f;
#pragma unroll
        for (int k8 = 0; k8 < 4; k8++) {
#pragma unroll
            for (int p = 0; p < 4; p++) {
                unsigned b00, b01, b10, b11;
                ldsm4t(b00, b01, b10, b11, uK + (k8 * 16 * KSTR + p * 16) * 2);
                mma16(s[2 * p],     qa[k8][0], qa[k8][1], qa[k8][2], qa[k8][3], b00, b01);
                mma16(s[2 * p + 1], qa[k8][0], qa[k8][1], qa[k8][2], qa[k8][3], b10, b11);
            }
        }

        // P = 2^s, local denominator (no max, no per-iter shuffles)
#pragma unroll
        for (int ni = 0; ni < 8; ni++) {
            s[ni][0] = ex2(s[ni][0]);
            s[ni][1] = ex2(s[ni][1]);
            s[ni][2] = ex2(s[ni][2]);
            s[ni][3] = ex2(s[ni][3]);
            rs0 += s[ni][0] + s[ni][1];
            rs1 += s[ni][2] + s[ni][3];
        }

        // O += P V : A-frag = S C-frag; V B-frags via non-trans ldmatrix
#pragma unroll
        for (int k8 = 0; k8 < 4; k8++) {
            unsigned a0 = pk(s[2 * k8][0],     s[2 * k8][1]);
            unsigned a1 = pk(s[2 * k8][2],     s[2 * k8][3]);
            unsigned a2 = pk(s[2 * k8 + 1][0], s[2 * k8 + 1][1]);
            unsigned a3 = pk(s[2 * k8 + 1][2], s[2 * k8 + 1][3]);
#pragma unroll
            for (int p = 0; p < 4; p++) {
                unsigned b0, b1, b2, b3;
                ldsm4(b0, b1, b2, b3, uV + (p * 16 * VSTR + k8 * 16) * 2);
                mma16(o[2 * p],     a0, a1, a2, a3, b0, b1);
                mma16(o[2 * p + 1], a0, a1, a2, a3, b2, b3);
            }
        }
        __syncthreads();   // all reads of buf done before overwrite
        buf ^= 1;
    }

    // Denominator reduction over the 4 lanes sharing lq
    rs0 += __shfl_xor_sync(0xffffffffu, rs0, 1);
    rs0 += __shfl_xor_sync(0xffffffffu, rs0, 2);
    rs1 += __shfl_xor_sync(0xffffffffu, rs1, 1);
    rs1 += __shfl_xor_sync(0xffffffffu, rs1, 2);
    const float inv0 = 1.f / rs0, inv1 = 1.f / rs1;

    // Epilogue: all cp.async drained (wait 0 at mt=31). Reuse smem front.
    __syncthreads();
    __nv_bfloat16* Es = (__nv_bfloat16*)smraw;   // [128][ESTR]
#pragma unroll
    for (int ni = 0; ni < 8; ni++) {
        const int col = ni * 8 + 2 * lk;
        *(unsigned*)&Es[(qw + lq) * ESTR + col]     = pk(o[ni][0] * inv0, o[ni][1] * inv0);
        *(unsigned*)&Es[(qw + 8 + lq) * ESTR + col] = pk(o[ni][2] * inv1, o[ni][3] * inv1);
    }
    __syncthreads();
    __nv_bfloat16* Ab = A + ((long)b * CH + h * HD) * NTOK + nq0;
#pragma unroll
    for (int r = 0; r < 4; r++) {
        int f = r * 256 + tid;
        int d = f >> 4, qc = (f & 15) * 8;
        unsigned short tmp[8];
#pragma unroll
        for (int j = 0; j < 8; j++)
            tmp[j] = *(const unsigned short*)&Es[(qc + j) * ESTR + d];
        *(uint4*)&Ab[(long)d * NTOK + qc] = *(uint4*)tmp;
    }
}

// ---------------------------------------------------------------------------
// LayerNorm: single gmem read, smem-cached.
// ---------------------------------------------------------------------------
#define LN_SMEM (512 * 36 * 4)
__global__ void __launch_bounds__(256, 2) ln512(
    const float* __restrict__ Z, const float* __restrict__ gamma,
    const float* __restrict__ beta, float* __restrict__ O)
{
    extern __shared__ float sc[];   // [512][36]
    __shared__ float ss[8][33], sq2[8][33];
    __shared__ float mu[32], rsd[32];
    const int tid = threadIdx.x;
    const int w = tid >> 5, l = tid & 31;
    const int n0 = blockIdx.x * 32;
    const int b = blockIdx.y;
    const float* Zb = Z + (long)b * CH * NTOK + n0;

#pragma unroll
    for (int k = 0; k < 16; k++) {
        int idx = k * 256 + tid;
        int c = idx >> 3, col = (idx & 7) * 4;
        float4 v = *(const float4*)&Zb[(long)c * NTOK + col];
        *(float4*)&sc[c * 36 + col] = v;
    }
    __syncthreads();

    float s = 0.f, q = 0.f;
#pragma unroll 8
    for (int c = w; c < CH; c += 8) {
        float v = sc[c * 36 + l];
        s += v; q += v * v;
    }
    ss[w][l] = s; sq2[w][l] = q;
    __syncthreads();
    if (w == 0) {
        float S = 0.f, Qq = 0.f;
#pragma unroll
        for (int i = 0; i < 8; i++) { S += ss[i][l]; Qq += sq2[i][l]; }
        float m = S * (1.f / CH);
        float var = Qq * (1.f / CH) - m * m;
        mu[l] = m;
        rsd[l] = rsqrtf(var + 1e-5f);
    }
    __syncthreads();

    float* Ob = O + (long)b * CH * NTOK + n0;
    const float M = mu[l], RS = rsd[l];
#pragma unroll 8
    for (int c = w; c < CH; c += 8) {
        float v = sc[c * 36 + l];
        Ob[(long)c * NTOK + l] = (v - M) * RS * gamma[c] + beta[c];
    }
}

// ---------------------------------------------------------------------------
extern "C" void kernel_launch(void* const* d_in, const int* in_sizes, int n_in,
                              void* d_out, int out_size)
{
    const float* f_curr = (const float*)d_in[0];
    const float* f_prev = (const float*)d_in[1];
    const float* f_next = (const float*)d_in[2];
    const float* Wq = (const float*)d_in[3];
    const float* Wk = (const float*)d_in[4];
    const float* Wv = (const float*)d_in[5];
    const float* Wo = (const float*)d_in[6];
    const float* gamma = (const float*)d_in[7];
    const float* beta = (const float*)d_in[8];
    float* out = (float*)d_out;

    __nv_bfloat16 *Qp, *Kp, *Vp, *Ap;
    float *Zp;
    cudaGetSymbolAddress((void**)&Qp, g_Q);
    cudaGetSymbolAddress((void**)&Kp, g_K);
    cudaGetSymbolAddress((void**)&Vp, g_V);
    cudaGetSymbolAddress((void**)&Ap, g_Abf);
    cudaGetSymbolAddress((void**)&Zp, g_Z);

    cudaFuncSetAttribute(flash_bf16, cudaFuncAttributeMaxDynamicSharedMemorySize,
                         FLASH_SMEM);
    cudaFuncSetAttribute(ln512, cudaFuncAttributeMaxDynamicSharedMemorySize,
                         LN_SMEM);

    // One-time input conversion to bf16
    cvt_all<<<dim3(2048, 7), 256>>>(f_curr, f_prev, f_next, Wq, Wk, Wv, Wo);

    // All 5 projections in one launch
    proj5<<<dim3(8, 4, 40), 256>>>();

    // Attention
    flash_bf16<<<dim3(8, HEADS, BATCH), 256, FLASH_SMEM>>>(Qp, Kp, Vp, Ap);

    // Output projection + residual
    gemm_wo<<<dim3(8, 4, 8), 256>>>(f_curr);

    // LayerNorm
    ln512<<<dim3(32, BATCH), 256, LN_SMEM>>>(Zp, gamma, beta, out);
}

// round 15
// speedup vs baseline: 1.4170x; 1.0435x over previous
#include <cuda_runtime.h>
#include <cuda_bf16.h>
#include <math.h>

// Shapes (fixed)
#define BATCH 8
#define CH    512
#define NTOK  1024
#define LKV   2048
#define HEADS 8
#define HD    64
#define SCALE 0.125f
#define LOG2E 1.44269504089f

// Scratch (static device allocations; no cudaMalloc allowed)
__device__ __nv_bfloat16 g_Q[BATCH * CH * NTOK];   // bf16, pre-scaled by 0.125*log2e
__device__ __nv_bfloat16 g_K[BATCH * CH * LKV];
__device__ __nv_bfloat16 g_V[BATCH * CH * LKV];
__device__ __nv_bfloat16 g_Abf[BATCH * CH * NTOK]; // attn out bf16
__device__ float g_Z[BATCH * CH * NTOK];
// bf16 copies of inputs
__device__ __nv_bfloat16 g_fc[BATCH * CH * NTOK];
__device__ __nv_bfloat16 g_fp[BATCH * CH * NTOK];
__device__ __nv_bfloat16 g_fn[BATCH * CH * NTOK];
__device__ __nv_bfloat16 g_wq[CH * CH];
__device__ __nv_bfloat16 g_wk[CH * CH];
__device__ __nv_bfloat16 g_wv[CH * CH];
__device__ __nv_bfloat16 g_wo[CH * CH];

// ---------------------------------------------------------------------------
// helpers
// ---------------------------------------------------------------------------
__device__ __forceinline__ unsigned pk(float lo, float hi) {
    __nv_bfloat162 t = __floats2bfloat162_rn(lo, hi);
    return *reinterpret_cast<unsigned*>(&t);
}
__device__ __forceinline__ unsigned s2u(const void* p) {
    return (unsigned)__cvta_generic_to_shared(p);
}
__device__ __forceinline__ float ex2(float x) {
    float y;
    asm("ex2.approx.f32 %0, %1;" : "=f"(y) : "f"(x));
    return y;
}
__device__ __forceinline__ void mma16(float* c,
                                      unsigned a0, unsigned a1, unsigned a2, unsigned a3,
                                      unsigned b0, unsigned b1) {
    asm volatile(
        "mma.sync.aligned.m16n8k16.row.col.f32.bf16.bf16.f32 "
        "{%0,%1,%2,%3}, {%4,%5,%6,%7}, {%8,%9}, {%0,%1,%2,%3};"
        : "+f"(c[0]), "+f"(c[1]), "+f"(c[2]), "+f"(c[3])
        : "r"(a0), "r"(a1), "r"(a2), "r"(a3), "r"(b0), "r"(b1));
}
__device__ __forceinline__ void ldsm4t(unsigned& r0, unsigned& r1,
                                       unsigned& r2, unsigned& r3, unsigned addr) {
    asm volatile("ldmatrix.sync.aligned.m8n8.x4.trans.shared.b16 {%0,%1,%2,%3}, [%4];"
                 : "=r"(r0), "=r"(r1), "=r"(r2), "=r"(r3) : "r"(addr));
}
__device__ __forceinline__ void ldsm4(unsigned& r0, unsigned& r1,
                                      unsigned& r2, unsigned& r3, unsigned addr) {
    asm volatile("ldmatrix.sync.aligned.m8n8.x4.shared.b16 {%0,%1,%2,%3}, [%4];"
                 : "=r"(r0), "=r"(r1), "=r"(r2), "=r"(r3) : "r"(addr));
}
__device__ __forceinline__ void cpa16(unsigned dst, const void* src) {
    asm volatile("cp.async.cg.shared.global [%0], [%1], 16;" :: "r"(dst), "l"(src));
}

// ---------------------------------------------------------------------------
// One-time fp32 -> bf16 conversions (features + weights, one launch)
// ---------------------------------------------------------------------------
__global__ void __launch_bounds__(256) cvt_all(
    const float* __restrict__ fc, const float* __restrict__ fp,
    const float* __restrict__ fn, const float* __restrict__ Wq,
    const float* __restrict__ Wk, const float* __restrict__ Wv,
    const float* __restrict__ Wo)
{
    const float* src; __nv_bfloat16* dst; long nElem;
    switch (blockIdx.y) {
        case 0: src = fc; dst = g_fc; nElem = (long)BATCH * CH * NTOK; break;
        case 1: src = fp; dst = g_fp; nElem = (long)BATCH * CH * NTOK; break;
        case 2: src = fn; dst = g_fn; nElem = (long)BATCH * CH * NTOK; break;
        case 3: src = Wq; dst = g_wq; nElem = CH * CH; break;
        case 4: src = Wk; dst = g_wk; nElem = CH * CH; break;
        case 5: src = Wv; dst = g_wv; nElem = CH * CH; break;
        default:src = Wo; dst = g_wo; nElem = CH * CH; break;
    }
    long i = ((long)blockIdx.x * 256 + threadIdx.x) * 8;
    if (i >= nElem) return;
    float4 a = *(const float4*)&src[i];
    float4 b = *(const float4*)&src[i + 4];
    uint4 u = make_uint4(pk(a.x, a.y), pk(a.z, a.w), pk(b.x, b.y), pk(b.z, b.w));
    *(uint4*)&dst[i] = u;
}

// ---------------------------------------------------------------------------
// GEMM core: 128x128 tile, k-step 32, 3-stage cp.async pipeline,
// SCALAR stage addressing (base + st*GSSB), one sync per iteration.
// ---------------------------------------------------------------------------
#define AST 40
#define BST 136
#define GA_ELTS (128 * AST)                 // 5120
#define GB_ELTS (32 * BST)                  // 4352
#define GSSB ((GA_ELTS + GB_ELTS) * 2)      // 18944 B per stage
#define GEMM_SMEM (3 * GSSB)                // 56832 B

template <bool OBF>
__device__ __forceinline__ void gemm_core(
    const __nv_bfloat16* __restrict__ W, const __nv_bfloat16* __restrict__ Xb,
    void* __restrict__ Obv, const float* __restrict__ Rb,
    int ldx, int ldc, int m0, int n0, float oscale)
{
    extern __shared__ __nv_bfloat16 gsm[];
    const int tid  = threadIdx.x;
    const int lane = tid & 31, warp = tid >> 5;
    const int wm = warp >> 2, wn = warp & 3;
    const int lq = lane >> 2, lk = lane & 3;
    const int t = lane >> 3, rr = lane & 7;

    float acc[4][4][4];
#pragma unroll
    for (int mi = 0; mi < 4; mi++)
#pragma unroll
        for (int ni = 0; ni < 4; ni++)
#pragma unroll
            for (int r = 0; r < 4; r++) acc[mi][ni][r] = 0.f;

    // Per-thread cp.async write addresses (stage 0) + gmem read bases
    const int c1 = 256 + tid;
    const int rA0 = tid >> 2, kA0 = (tid & 3) * 8;
    const int rA1 = c1 >> 2,  kA1 = (c1 & 3) * 8;
    const int rB0 = tid >> 4, nB0 = (tid & 15) * 8;
    const int rB1 = c1 >> 4,  nB1 = (c1 & 15) * 8;
    const unsigned sbase = s2u(gsm);
    const unsigned wA0 = sbase + (rA0 * AST + kA0) * 2;
    const unsigned wA1 = sbase + (rA1 * AST + kA1) * 2;
    const unsigned wB0 = sbase + (GA_ELTS + rB0 * BST + nB0) * 2;
    const unsigned wB1 = sbase + (GA_ELTS + rB1 * BST + nB1) * 2;
    const __nv_bfloat16* gA0 = W + (long)(m0 + rA0) * 512 + kA0;
    const __nv_bfloat16* gA1 = W + (long)(m0 + rA1) * 512 + kA1;
    const __nv_bfloat16* gB0 = Xb + (long)rB0 * ldx + n0 + nB0;
    const __nv_bfloat16* gB1 = Xb + (long)rB1 * ldx + n0 + nB1;

    auto issue = [&](int st, int k0) {
        const unsigned o = (unsigned)st * GSSB;
        cpa16(wA0 + o, gA0 + k0);
        cpa16(wA1 + o, gA1 + k0);
        cpa16(wB0 + o, gB0 + (long)k0 * ldx);
        cpa16(wB1 + o, gB1 + (long)k0 * ldx);
        asm volatile("cp.async.commit_group;");
    };

    // Per-thread ldmatrix read bases (stage 0)
    const unsigned ath = (unsigned)(((wm * 64 + rr + (t & 1) * 8) * AST + (t >> 1) * 8) * 2);
    const unsigned bth = (unsigned)(((rr + (t & 1) * 8) * BST + wn * 32 + (t >> 1) * 8) * 2);
    const unsigned uAr = sbase + ath;
    const unsigned uBr = sbase + GA_ELTS * 2 + bth;

    issue(0, 0);
    issue(1, 32);

    int st = 0, st2 = 2;
    for (int it = 0; it < 16; it++) {
        if (it == 15) asm volatile("cp.async.wait_group 0;");
        else          asm volatile("cp.async.wait_group 1;");
        __syncthreads();

        // Prefetch stage it+2 (the stage consumed at it-1; safe past sync(it))
        if (it + 2 < 16) issue(st2, (it + 2) * 32);

        const unsigned uA = uAr + (unsigned)st * GSSB;
        const unsigned uB = uBr + (unsigned)st * GSSB;
#pragma unroll
        for (int ss = 0; ss < 2; ss++) {
            const int kb = ss * 16;
            unsigned af[4][4];
#pragma unroll
            for (int mi = 0; mi < 4; mi++)
                ldsm4(af[mi][0], af[mi][1], af[mi][2], af[mi][3],
                      uA + (mi * 16 * AST + kb) * 2);
            unsigned bfv[4][2];
#pragma unroll
            for (int p = 0; p < 2; p++)
                ldsm4t(bfv[2 * p][0], bfv[2 * p][1], bfv[2 * p + 1][0], bfv[2 * p + 1][1],
                       uB + (kb * BST + p * 16) * 2);
#pragma unroll
            for (int mi = 0; mi < 4; mi++)
#pragma unroll
                for (int ni = 0; ni < 4; ni++)
                    mma16(acc[mi][ni], af[mi][0], af[mi][1], af[mi][2], af[mi][3],
                          bfv[ni][0], bfv[ni][1]);
        }
        st  = (st  == 2) ? 0 : st  + 1;
        st2 = (st2 == 2) ? 0 : st2 + 1;
    }

#pragma unroll
    for (int mi = 0; mi < 4; mi++) {
#pragma unroll
        for (int ni = 0; ni < 4; ni++) {
            const int row = m0 + wm * 64 + mi * 16 + lq;
            const int col = n0 + wn * 32 + ni * 8 + 2 * lk;
            const long o0 = (long)row * ldc + col;
            const long o1 = (long)(row + 8) * ldc + col;
            if (OBF) {
                __nv_bfloat16* Ob = (__nv_bfloat16*)Obv;
                *(unsigned*)&Ob[o0] = pk(acc[mi][ni][0] * oscale, acc[mi][ni][1] * oscale);
                *(unsigned*)&Ob[o1] = pk(acc[mi][ni][2] * oscale, acc[mi][ni][3] * oscale);
            } else {
                float* Ob = (float*)Obv;
                float2 v0 = make_float2(acc[mi][ni][0], acc[mi][ni][1]);
                float2 v1 = make_float2(acc[mi][ni][2], acc[mi][ni][3]);
                float2 r0 = *(const float2*)&Rb[o0];
                float2 r1 = *(const float2*)&Rb[o1];
                v0.x += r0.x; v0.y += r0.y;
                v1.x += r1.x; v1.y += r1.y;
                *(float2*)&Ob[o0] = v0;
                *(float2*)&Ob[o1] = v1;
            }
        }
    }
}

// All 5 projections in ONE launch; Q pre-scaled by 0.125*log2e
__global__ void __launch_bounds__(256, 2) proj5()
{
    const int z = blockIdx.z;
    const int b = z & 7, job = z >> 3;
    const long sN = (long)CH * NTOK, sL = (long)CH * LKV;
    const __nv_bfloat16* W; const __nv_bfloat16* X; __nv_bfloat16* O;
    int ldc; float osc = 1.f;
    switch (job) {
        case 0: W = g_wq; X = g_fc + b * sN; O = g_Q + b * sN;        ldc = NTOK; osc = SCALE * LOG2E; break;
        case 1: W = g_wk; X = g_fp + b * sN; O = g_K + b * sL;        ldc = LKV;  break;
        case 2: W = g_wk; X = g_fn + b * sN; O = g_K + b * sL + NTOK; ldc = LKV;  break;
        case 3: W = g_wv; X = g_fp + b * sN; O = g_V + b * sL;        ldc = LKV;  break;
        default:W = g_wv; X = g_fn + b * sN; O = g_V + b * sL + NTOK; ldc = LKV;  break;
    }
    gemm_core<true>(W, X, O, nullptr, NTOK, ldc, blockIdx.y * 128, blockIdx.x * 128, osc);
}

// Output projection + residual
__global__ void __launch_bounds__(256, 2) gemm_wo(const float* __restrict__ R)
{
    const long sN = (long)CH * NTOK;
    gemm_core<false>(g_wo, g_Abf + blockIdx.z * sN, g_Z + blockIdx.z * sN,
                     R + blockIdx.z * sN, NTOK, NTOK,
                     blockIdx.y * 128, blockIdx.x * 128, 1.f);
}

// ---------------------------------------------------------------------------
// Flash attention: 3-stage KV pipeline with scalar stage addressing,
// one sync per iter; ldmatrix K (trans) + V (non-trans); P in registers;
// exp2-domain softmax without online max.
// ---------------------------------------------------------------------------
#define QSTR 136
#define KSTR 72
#define VSTR 72
#define ESTR 72
#define Q_ELTS (64 * QSTR)
#define K_ELTS (64 * KSTR)
#define V_ELTS (64 * VSTR)
#define KVB ((K_ELTS + V_ELTS) * 2)                    // 18432 B per stage
#define FLASH_SMEM (Q_ELTS * 2 + 3 * KVB)              // 72704 B

__global__ void __launch_bounds__(256, 2) flash_bf16(
    const __nv_bfloat16* __restrict__ Q, const __nv_bfloat16* __restrict__ K,
    const __nv_bfloat16* __restrict__ V, __nv_bfloat16* __restrict__ A)
{
    extern __shared__ char smraw[];
    __nv_bfloat16* Qs = (__nv_bfloat16*)smraw;
    __nv_bfloat16* KV0 = Qs + Q_ELTS;   // stage s: [K | V] at KV0 + s*(K+V)

    const int tid  = threadIdx.x;
    const int lane = tid & 31;
    const int warp = tid >> 5;
    const int qw = warp * 16;
    const int lq = lane >> 2, lk = lane & 3;
    const int t = lane >> 3, rr = lane & 7;
    const int nq0 = blockIdx.x * 128;
    const int h = blockIdx.y, b = blockIdx.z;

    const __nv_bfloat16* Qb = Q + ((long)b * CH + h * HD) * NTOK + nq0;
    const __nv_bfloat16* Kb = K + ((long)b * CH + h * HD) * LKV;
    const __nv_bfloat16* Vb = V + ((long)b * CH + h * HD) * LKV;

    // Per-thread KV cp.async write addresses (stage 0) + gmem bases
    const int c1 = 256 + tid;
    const int d0 = tid >> 3, e0 = (tid & 7) * 8;
    const int d1 = c1 >> 3,  e1 = (c1 & 7) * 8;
    const unsigned kv0 = s2u(KV0);
    const unsigned wK0 = kv0 + (d0 * KSTR + e0) * 2;
    const unsigned wK1 = kv0 + (d1 * KSTR + e1) * 2;
    const unsigned wV0 = wK0 + K_ELTS * 2;
    const unsigned wV1 = wK1 + K_ELTS * 2;
    const __nv_bfloat16* gK0 = Kb + (long)d0 * LKV + e0;
    const __nv_bfloat16* gK1 = Kb + (long)d1 * LKV + e1;
    const __nv_bfloat16* gV0 = Vb + (long)d0 * LKV + e0;
    const __nv_bfloat16* gV1 = Vb + (long)d1 * LKV + e1;

    auto kv_issue = [&](int st, int m0k) {
        const unsigned o = (unsigned)st * KVB;
        cpa16(wK0 + o, gK0 + m0k);
        cpa16(wK1 + o, gK1 + m0k);
        cpa16(wV0 + o, gV0 + m0k);
        cpa16(wV1 + o, gV1 + m0k);
        asm volatile("cp.async.commit_group;");
    };

    // Prologue: Q group, then KV stages 0,1
#pragma unroll
    for (int r = 0; r < 4; r++) {
        int f = r * 256 + tid;
        int d = f >> 4, e = (f & 15) * 8;
        cpa16(s2u(&Qs[d * QSTR + e]), Qb + (long)d * NTOK + e);
    }
    asm volatile("cp.async.commit_group;");
    kv_issue(0, 0);
    kv_issue(1, 64);

    // Wait Q, hoist Q fragments (loop-invariant)
    asm volatile("cp.async.wait_group 2;");
    __syncthreads();
    unsigned qa[4][4];
    {
        const unsigned qbase = s2u(Qs) +
            ((rr + (t >> 1) * 8) * QSTR + qw + (t & 1) * 8) * 2;
#pragma unroll
        for (int k8 = 0; k8 < 4; k8++)
            ldsm4t(qa[k8][0], qa[k8][1], qa[k8][2], qa[k8][3],
                   qbase + k8 * 16 * QSTR * 2);
    }

    // Per-thread ldmatrix read bases (stage 0)
    const unsigned kth = ((rr + (t & 1) * 8) * KSTR + (t >> 1) * 8) * 2;   // trans
    const unsigned vth = ((rr + (t >> 1) * 8) * VSTR + (t & 1) * 8) * 2;   // non-trans
    const unsigned uKr = kv0 + kth;
    const unsigned uVr = kv0 + K_ELTS * 2 + vth;

    float o[8][4];
#pragma unroll
    for (int ni = 0; ni < 8; ni++)
#pragma unroll
        for (int r = 0; r < 4; r++) o[ni][r] = 0.f;
    float rs0 = 0.f, rs1 = 0.f;

    int st = 0, st2 = 2;
    for (int mt = 0; mt < 32; mt++) {
        if (mt == 31) asm volatile("cp.async.wait_group 0;");
        else          asm volatile("cp.async.wait_group 1;");
        __syncthreads();

        // Prefetch KV(mt+2) into stage consumed at mt-1 (safe past sync(mt))
        if (mt + 2 < 32) kv_issue(st2, (mt + 2) * 64);

        const unsigned uK = uKr + (unsigned)st * KVB;
        const unsigned uV = uVr + (unsigned)st * KVB;

        // S = Q^T K : q16 x kv64 (log2 units)
        float s[8][4];
#pragma unroll
        for (int ni = 0; ni < 8; ni++)
#pragma unroll
            for (int r = 0; r < 4; r++) s[ni][r] = 0.f;
#pragma unroll
        for (int k8 = 0; k8 < 4; k8++) {
#pragma unroll
            for (int p = 0; p < 4; p++) {
                unsigned b00, b01, b10, b11;
                ldsm4t(b00, b01, b10, b11, uK + (k8 * 16 * KSTR + p * 16) * 2);
                mma16(s[2 * p],     qa[k8][0], qa[k8][1], qa[k8][2], qa[k8][3], b00, b01);
                mma16(s[2 * p + 1], qa[k8][0], qa[k8][1], qa[k8][2], qa[k8][3], b10, b11);
            }
        }

        // P = 2^s, local denominator (no max, no per-iter shuffles)
#pragma unroll
        for (int ni = 0; ni < 8; ni++) {
            s[ni][0] = ex2(s[ni][0]);
            s[ni][1] = ex2(s[ni][1]);
            s[ni][2] = ex2(s[ni][2]);
            s[ni][3] = ex2(s[ni][3]);
            rs0 += s[ni][0] + s[ni][1];
            rs1 += s[ni][2] + s[ni][3];
        }

        // O += P V : A-frag = S C-frag; V B-frags via non-trans ldmatrix
#pragma unroll
        for (int k8 = 0; k8 < 4; k8++) {
            unsigned a0 = pk(s[2 * k8][0],     s[2 * k8][1]);
            unsigned a1 = pk(s[2 * k8][2],     s[2 * k8][3]);
            unsigned a2 = pk(s[2 * k8 + 1][0], s[2 * k8 + 1][1]);
            unsigned a3 = pk(s[2 * k8 + 1][2], s[2 * k8 + 1][3]);
#pragma unroll
            for (int p = 0; p < 4; p++) {
                unsigned b0, b1, b2, b3;
                ldsm4(b0, b1, b2, b3, uV + (p * 16 * VSTR + k8 * 16) * 2);
                mma16(o[2 * p],     a0, a1, a2, a3, b0, b1);
                mma16(o[2 * p + 1], a0, a1, a2, a3, b2, b3);
            }
        }
        st  = (st  == 2) ? 0 : st  + 1;
        st2 = (st2 == 2) ? 0 : st2 + 1;
    }

    // Denominator reduction over the 4 lanes sharing lq
    rs0 += __shfl_xor_sync(0xffffffffu, rs0, 1);
    rs0 += __shfl_xor_sync(0xffffffffu, rs0, 2);
    rs1 += __shfl_xor_sync(0xffffffffu, rs1, 1);
    rs1 += __shfl_xor_sync(0xffffffffu, rs1, 2);
    const float inv0 = 1.f / rs0, inv1 = 1.f / rs1;

    // Epilogue: all cp.async drained (wait 0 at mt=31). Reuse smem front (Qs).
    __syncthreads();
    __nv_bfloat16* Es = (__nv_bfloat16*)smraw;   // [128][ESTR]
#pragma unroll
    for (int ni = 0; ni < 8; ni++) {
        const int col = ni * 8 + 2 * lk;
        *(unsigned*)&Es[(qw + lq) * ESTR + col]     = pk(o[ni][0] * inv0, o[ni][1] * inv0);
        *(unsigned*)&Es[(qw + 8 + lq) * ESTR + col] = pk(o[ni][2] * inv1, o[ni][3] * inv1);
    }
    __syncthreads();
    __nv_bfloat16* Ab = A + ((long)b * CH + h * HD) * NTOK + nq0;
#pragma unroll
    for (int r = 0; r < 4; r++) {
        int f = r * 256 + tid;
        int d = f >> 4, qc = (f & 15) * 8;
        unsigned short tmp[8];
#pragma unroll
        for (int j = 0; j < 8; j++)
            tmp[j] = *(const unsigned short*)&Es[(qc + j) * ESTR + d];
        *(uint4*)&Ab[(long)d * NTOK + qc] = *(uint4*)tmp;
    }
}

// ---------------------------------------------------------------------------
// LayerNorm: single gmem read, smem-cached.
// ---------------------------------------------------------------------------
#define LN_SMEM (512 * 36 * 4)
__global__ void __launch_bounds__(256, 2) ln512(
    const float* __restrict__ Z, const float* __restrict__ gamma,
    const float* __restrict__ beta, float* __restrict__ O)
{
    extern __shared__ float sc[];   // [512][36]
    __shared__ float ss[8][33], sq2[8][33];
    __shared__ float mu[32], rsd[32];
    const int tid = threadIdx.x;
    const int w = tid >> 5, l = tid & 31;
    const int n0 = blockIdx.x * 32;
    const int b = blockIdx.y;
    const float* Zb = Z + (long)b * CH * NTOK + n0;

#pragma unroll
    for (int k = 0; k < 16; k++) {
        int idx = k * 256 + tid;
        int c = idx >> 3, col = (idx & 7) * 4;
        float4 v = *(const float4*)&Zb[(long)c * NTOK + col];
        *(float4*)&sc[c * 36 + col] = v;
    }
    __syncthreads();

    float s = 0.f, q = 0.f;
#pragma unroll 8
    for (int c = w; c < CH; c += 8) {
        float v = sc[c * 36 + l];
        s += v; q += v * v;
    }
    ss[w][l] = s; sq2[w][l] = q;
    __syncthreads();
    if (w == 0) {
        float S = 0.f, Qq = 0.f;
#pragma unroll
        for (int i = 0; i < 8; i++) { S += ss[i][l]; Qq += sq2[i][l]; }
        float m = S * (1.f / CH);
        float var = Qq * (1.f / CH) - m * m;
        mu[l] = m;
        rsd[l] = rsqrtf(var + 1e-5f);
    }
    __syncthreads();

    float* Ob = O + (long)b * CH * NTOK + n0;
    const float M = mu[l], RS = rsd[l];
#pragma unroll 8
    for (int c = w; c < CH; c += 8) {
        float v = sc[c * 36 + l];
        Ob[(long)c * NTOK + l] = (v - M) * RS * gamma[c] + beta[c];
    }
}

// ---------------------------------------------------------------------------
extern "C" void kernel_launch(void* const* d_in, const int* in_sizes, int n_in,
                              void* d_out, int out_size)
{
    const float* f_curr = (const float*)d_in[0];
    const float* f_prev = (const float*)d_in[1];
    const float* f_next = (const float*)d_in[2];
    const float* Wq = (const float*)d_in[3];
    const float* Wk = (const float*)d_in[4];
    const float* Wv = (const float*)d_in[5];
    const float* Wo = (const float*)d_in[6];
    const float* gamma = (const float*)d_in[7];
    const float* beta = (const float*)d_in[8];
    float* out = (float*)d_out;

    __nv_bfloat16 *Qp, *Kp, *Vp, *Ap;
    float *Zp;
    cudaGetSymbolAddress((void**)&Qp, g_Q);
    cudaGetSymbolAddress((void**)&Kp, g_K);
    cudaGetSymbolAddress((void**)&Vp, g_V);
    cudaGetSymbolAddress((void**)&Ap, g_Abf);
    cudaGetSymbolAddress((void**)&Zp, g_Z);

    cudaFuncSetAttribute(proj5, cudaFuncAttributeMaxDynamicSharedMemorySize, GEMM_SMEM);
    cudaFuncSetAttribute(gemm_wo, cudaFuncAttributeMaxDynamicSharedMemorySize, GEMM_SMEM);
    cudaFuncSetAttribute(flash_bf16, cudaFuncAttributeMaxDynamicSharedMemorySize, FLASH_SMEM);
    cudaFuncSetAttribute(ln512, cudaFuncAttributeMaxDynamicSharedMemorySize, LN_SMEM);

    // One-time input conversion to bf16
    cvt_all<<<dim3(2048, 7), 256>>>(f_curr, f_prev, f_next, Wq, Wk, Wv, Wo);

    // All 5 projections in one launch
    proj5<<<dim3(8, 4, 40), 256, GEMM_SMEM>>>();

    // Attention
    flash_bf16<<<dim3(8, HEADS, BATCH), 256, FLASH_SMEM>>>(Qp, Kp, Vp, Ap);

    // Output projection + residual
    gemm_wo<<<dim3(8, 4, 8), 256, GEMM_SMEM>>>(f_curr);

    // LayerNorm
    ln512<<<dim3(32, BATCH), 256, LN_SMEM>>>(Zp, gamma, beta, out);
}